// round 1
// baseline (speedup 1.0000x reference)
#include <cuda_runtime.h>
#include <math.h>

#define H       128
#define TI      8     // interior points per block
#define TB      32    // boundary points per block
#define THREADS 256

// Per-block partial sums (deterministic two-stage reduction; no device mallocs)
__device__ float g_part_int[65536];
__device__ float g_part_bd[8192];

// Accurate-enough tanh that is independent of -use_fast_math lowering of tanhf.
// __expf rel error ~1e-6 for our argument range; chain through 2nd derivatives stays << 1e-3.
__device__ __forceinline__ float my_tanh(float x)
{
    float ax = fabsf(x);
    float t  = __expf(-2.0f * ax);
    float r  = (1.0f - t) / (1.0f + t);
    return copysignf(r, x);
}

// ---------------------------------------------------------------------------
// Hidden layer, 5 channels (v, gx, gy, hxx, hyy), TI points per block.
// in/out layout: [channel][point][unit] contiguous in unit (k).
// Thread j computes output unit j for 4 points (its half) x 5 channels.
// ---------------------------------------------------------------------------
__device__ __forceinline__ void hidden5(const float* __restrict__ in,
                                        float* __restrict__ outp,
                                        const float* __restrict__ W,
                                        const float* __restrict__ b,
                                        int j, int p0)
{
    float acc[5][TI / 2];
#pragma unroll
    for (int c = 0; c < 5; c++)
#pragma unroll
        for (int p = 0; p < TI / 2; p++) acc[c][p] = 0.0f;

#pragma unroll 1
    for (int k = 0; k < H; k += 4) {
        const float w0 = W[(k + 0) * H + j];
        const float w1 = W[(k + 1) * H + j];
        const float w2 = W[(k + 2) * H + j];
        const float w3 = W[(k + 3) * H + j];
#pragma unroll
        for (int c = 0; c < 5; c++) {
#pragma unroll
            for (int p = 0; p < TI / 2; p++) {
                const float4 a = *reinterpret_cast<const float4*>(
                    &in[((c * TI) + (p0 + p)) * H + k]);
                acc[c][p] = fmaf(a.x, w0,
                             fmaf(a.y, w1,
                              fmaf(a.z, w2,
                               fmaf(a.w, w3, acc[c][p]))));
            }
        }
    }

    const float bj = b[j];
#pragma unroll
    for (int p = 0; p < TI / 2; p++) {
        const int pp = p0 + p;
        float zv  = acc[0][p] + bj;
        float zgx = acc[1][p];
        float zgy = acc[2][p];
        float zxx = acc[3][p];
        float zyy = acc[4][p];
        float a  = my_tanh(zv);
        float t1 = 1.0f - a * a;
        float t2 = -2.0f * a * t1;
        outp[(0 * TI + pp) * H + j] = a;
        outp[(1 * TI + pp) * H + j] = t1 * zgx;
        outp[(2 * TI + pp) * H + j] = t1 * zgy;
        outp[(3 * TI + pp) * H + j] = fmaf(t2 * zgx, zgx, t1 * zxx);
        outp[(4 * TI + pp) * H + j] = fmaf(t2 * zgy, zgy, t1 * zyy);
    }
}

// ---------------------------------------------------------------------------
// Hidden layer, value channel only, TB points per block (boundary path).
// ---------------------------------------------------------------------------
__device__ __forceinline__ void hidden1(const float* __restrict__ in,
                                        float* __restrict__ outp,
                                        const float* __restrict__ W,
                                        const float* __restrict__ b,
                                        int j, int p0)
{
    float acc[TB / 2];
#pragma unroll
    for (int p = 0; p < TB / 2; p++) acc[p] = 0.0f;

#pragma unroll 1
    for (int k = 0; k < H; k += 4) {
        const float w0 = W[(k + 0) * H + j];
        const float w1 = W[(k + 1) * H + j];
        const float w2 = W[(k + 2) * H + j];
        const float w3 = W[(k + 3) * H + j];
#pragma unroll
        for (int p = 0; p < TB / 2; p++) {
            const float4 a = *reinterpret_cast<const float4*>(
                &in[(p0 + p) * H + k]);
            acc[p] = fmaf(a.x, w0,
                      fmaf(a.y, w1,
                       fmaf(a.z, w2,
                        fmaf(a.w, w3, acc[p]))));
        }
    }

    const float bj = b[j];
#pragma unroll
    for (int p = 0; p < TB / 2; p++)
        outp[(p0 + p) * H + j] = my_tanh(acc[p] + bj);
}

// ---------------------------------------------------------------------------
// Interior: Taylor-mode Laplacian + squared residual partial sums.
// ---------------------------------------------------------------------------
__global__ __launch_bounds__(THREADS)
void pinn_interior(const float* __restrict__ xy, const float* __restrict__ f,
                   const float* __restrict__ W0, const float* __restrict__ b0,
                   const float* __restrict__ W1, const float* __restrict__ b1,
                   const float* __restrict__ W2, const float* __restrict__ b2,
                   const float* __restrict__ W3, int n)
{
    __shared__ float A[5 * TI * H];
    __shared__ float B[5 * TI * H];
    __shared__ float sxy[TI * 2];
    __shared__ float red[H * TI];

    const int tid  = threadIdx.x;
    const int j    = tid & (H - 1);
    const int p0   = (tid >> 7) * (TI / 2);
    const int base = blockIdx.x * TI;

    if (tid < TI * 2) {
        int pt = base + (tid >> 1);
        if (pt > n - 1) pt = n - 1;
        sxy[tid] = xy[pt * 2 + (tid & 1)];
    }
    __syncthreads();

    // ---- layer 0: input (x,y) -> 128, with derivative seeding ----
    {
        const float w0x = W0[j];
        const float w0y = W0[H + j];
        const float bj  = b0[j];
#pragma unroll
        for (int p = 0; p < TI / 2; p++) {
            const int pp = p0 + p;
            float x  = sxy[pp * 2 + 0];
            float y  = sxy[pp * 2 + 1];
            float zv = fmaf(x, w0x, fmaf(y, w0y, bj));
            float a  = my_tanh(zv);
            float t1 = 1.0f - a * a;
            float t2 = -2.0f * a * t1;
            A[(0 * TI + pp) * H + j] = a;
            A[(1 * TI + pp) * H + j] = t1 * w0x;       // gx
            A[(2 * TI + pp) * H + j] = t1 * w0y;       // gy
            A[(3 * TI + pp) * H + j] = t2 * w0x * w0x; // hxx
            A[(4 * TI + pp) * H + j] = t2 * w0y * w0y; // hyy
        }
    }
    __syncthreads();

    hidden5(A, B, W1, b1, j, p0);
    __syncthreads();
    hidden5(B, A, W2, b2, j, p0);
    __syncthreads();

    // ---- output layer: lap = (hxx + hyy) . W3 (bias has zero Laplacian) ----
    if (tid < H) {
        const float w3j = W3[j];
#pragma unroll
        for (int p = 0; p < TI; p++)
            red[j * TI + p] =
                (A[(3 * TI + p) * H + j] + A[(4 * TI + p) * H + j]) * w3j;
    }
    __syncthreads();
#pragma unroll
    for (int s = 64; s > 0; s >>= 1) {
        if (tid < H && j < s) {
#pragma unroll
            for (int p = 0; p < TI; p++)
                red[j * TI + p] += red[(j + s) * TI + p];
        }
        __syncthreads();
    }

    if (tid == 0) {
        float ssum = 0.0f;
#pragma unroll
        for (int p = 0; p < TI; p++) {
            int idx = base + p;
            if (idx < n) {
                float d = red[p] - f[idx];
                ssum = fmaf(d, d, ssum);
            }
        }
        g_part_int[blockIdx.x] = ssum;
    }
}

// ---------------------------------------------------------------------------
// Boundary: plain forward + squared residual partial sums.
// ---------------------------------------------------------------------------
__global__ __launch_bounds__(THREADS)
void pinn_boundary(const float* __restrict__ xy, const float* __restrict__ g,
                   const float* __restrict__ W0, const float* __restrict__ b0,
                   const float* __restrict__ W1, const float* __restrict__ b1,
                   const float* __restrict__ W2, const float* __restrict__ b2,
                   const float* __restrict__ W3, const float* __restrict__ b3,
                   int n)
{
    __shared__ float A[TB * H];
    __shared__ float B[TB * H];
    __shared__ float sxy[TB * 2];
    __shared__ float red[TB];

    const int tid  = threadIdx.x;
    const int j    = tid & (H - 1);
    const int p0   = (tid >> 7) * (TB / 2);
    const int base = blockIdx.x * TB;

    if (tid < TB * 2) {
        int pt = base + (tid >> 1);
        if (pt > n - 1) pt = n - 1;
        sxy[tid] = xy[pt * 2 + (tid & 1)];
    }
    __syncthreads();

    {
        const float w0x = W0[j];
        const float w0y = W0[H + j];
        const float bj  = b0[j];
#pragma unroll
        for (int p = 0; p < TB / 2; p++) {
            const int pp = p0 + p;
            float x = sxy[pp * 2 + 0];
            float y = sxy[pp * 2 + 1];
            A[pp * H + j] = my_tanh(fmaf(x, w0x, fmaf(y, w0y, bj)));
        }
    }
    __syncthreads();

    hidden1(A, B, W1, b1, j, p0);
    __syncthreads();
    hidden1(B, A, W2, b2, j, p0);
    __syncthreads();

    if (tid < TB) {
        float v = b3[0];
        for (int k = 0; k < H; k++)
            v = fmaf(A[tid * H + k], W3[k], v);
        int idx = base + tid;
        float d = 0.0f;
        if (idx < n) {
            d = v - g[idx];
            red[tid] = d * d;
        } else {
            red[tid] = 0.0f;
        }
    }
    __syncthreads();

    if (tid == 0) {
        float s = 0.0f;
#pragma unroll
        for (int p = 0; p < TB; p++) s += red[p];
        g_part_bd[blockIdx.x] = s;
    }
}

// ---------------------------------------------------------------------------
// Final deterministic reduction -> out[0] = loss_bound, out[1] = loss_f
// ---------------------------------------------------------------------------
__global__ __launch_bounds__(THREADS)
void pinn_finalize(float* __restrict__ out, int nbi, int nbb,
                   int n_int, int n_bd)
{
    __shared__ float s[THREADS];
    const int tid = threadIdx.x;

    float a = 0.0f;
    for (int i = tid; i < nbi; i += THREADS) a += g_part_int[i];
    s[tid] = a;
    __syncthreads();
    for (int st = THREADS / 2; st > 0; st >>= 1) {
        if (tid < st) s[tid] += s[tid + st];
        __syncthreads();
    }
    float loss_f = 0.0f;
    if (tid == 0) loss_f = s[0] * (0.5f / (float)n_int);
    __syncthreads();

    float bsm = 0.0f;
    for (int i = tid; i < nbb; i += THREADS) bsm += g_part_bd[i];
    s[tid] = bsm;
    __syncthreads();
    for (int st = THREADS / 2; st > 0; st >>= 1) {
        if (tid < st) s[tid] += s[tid + st];
        __syncthreads();
    }
    if (tid == 0) {
        out[0] = s[0] * (0.5f / (float)n_bd); // loss_bound
        out[1] = loss_f;                      // loss_f
    }
}

// ---------------------------------------------------------------------------
extern "C" void kernel_launch(void* const* d_in, const int* in_sizes, int n_in,
                              void* d_out, int out_size)
{
    const float* xy_int = (const float*)d_in[0];
    const float* f      = (const float*)d_in[1];
    const float* xy_bd  = (const float*)d_in[2];
    const float* g      = (const float*)d_in[3];
    const float* W0     = (const float*)d_in[4];
    const float* b0     = (const float*)d_in[5];
    const float* W1     = (const float*)d_in[6];
    const float* b1     = (const float*)d_in[7];
    const float* W2     = (const float*)d_in[8];
    const float* b2     = (const float*)d_in[9];
    const float* W3     = (const float*)d_in[10];
    const float* b3     = (const float*)d_in[11];

    const int n_int = in_sizes[0] / 2;
    const int n_bd  = in_sizes[2] / 2;

    int gi = (n_int + TI - 1) / TI;
    int gb = (n_bd + TB - 1) / TB;
    if (gi > 65536) gi = 65536; // scratch bound (dataset: 32768)
    if (gb > 8192)  gb = 8192;  // scratch bound (dataset: 512)

    pinn_interior<<<gi, THREADS>>>(xy_int, f, W0, b0, W1, b1, W2, b2, W3, n_int);
    pinn_boundary<<<gb, THREADS>>>(xy_bd, g, W0, b0, W1, b1, W2, b2, W3, b3, n_bd);
    pinn_finalize<<<1, THREADS>>>((float*)d_out, gi, gb, n_int, n_bd);
}

// round 2
// speedup vs baseline: 1.4596x; 1.4596x over previous
#include <cuda_runtime.h>
#include <math.h>

#define H       128
#define TI      16    // interior points per block
#define TB      32    // boundary points per block
#define THREADS 256

// Per-block partial sums (deterministic two-stage reduction; no device mallocs)
__device__ float g_part_int[65536];
__device__ float g_part_bd[8192];

// Accurate tanh independent of -use_fast_math lowering of tanhf.
__device__ __forceinline__ float my_tanh(float x)
{
    float ax = fabsf(x);
    float t  = __expf(-2.0f * ax);
    float r  = (1.0f - t) / (1.0f + t);
    return copysignf(r, x);
}

// Dynamic smem layout (floats):
//   A   [5*TI*H]      = 10240
//   B   [5*TI*H]      = 10240
//   sxy [TI*2]        = 32
//   slap[TI]          = 16
#define SM_A    0
#define SM_B    (5 * TI * H)
#define SM_XY   (2 * 5 * TI * H)
#define SM_LAP  (SM_XY + TI * 2)
#define SM_FLOATS (SM_LAP + TI)

// ---------------------------------------------------------------------------
// Hidden layer core: accumulate 5 channels x 2 points x 4 units.
// t = tid&31 selects unit group j = 4t..4t+3 (warp covers all 128 units),
// pp0 = (tid>>5)*2 selects the 2 points (8 warps cover 16 points).
// Activation loads are lane-uniform (smem broadcast); weight loads are
// LDG.128, warp-contiguous 512B.
// ---------------------------------------------------------------------------
__device__ __forceinline__ void accum5(const float* __restrict__ in,
                                       const float* __restrict__ W,
                                       int j4, int pp0,
                                       float acc[5][2][4])
{
#pragma unroll
    for (int c = 0; c < 5; c++)
#pragma unroll
        for (int p = 0; p < 2; p++)
#pragma unroll
            for (int u = 0; u < 4; u++) acc[c][p][u] = 0.0f;

#pragma unroll 1
    for (int k = 0; k < H; k += 4) {
        const float4 w0 = *reinterpret_cast<const float4*>(&W[(k + 0) * H + j4]);
        const float4 w1 = *reinterpret_cast<const float4*>(&W[(k + 1) * H + j4]);
        const float4 w2 = *reinterpret_cast<const float4*>(&W[(k + 2) * H + j4]);
        const float4 w3 = *reinterpret_cast<const float4*>(&W[(k + 3) * H + j4]);
#pragma unroll
        for (int c = 0; c < 5; c++) {
#pragma unroll
            for (int p = 0; p < 2; p++) {
                const float4 a = *reinterpret_cast<const float4*>(
                    &in[(c * TI + pp0 + p) * H + k]);
                acc[c][p][0] = fmaf(a.x, w0.x, fmaf(a.y, w1.x,
                               fmaf(a.z, w2.x, fmaf(a.w, w3.x, acc[c][p][0]))));
                acc[c][p][1] = fmaf(a.x, w0.y, fmaf(a.y, w1.y,
                               fmaf(a.z, w2.y, fmaf(a.w, w3.y, acc[c][p][1]))));
                acc[c][p][2] = fmaf(a.x, w0.z, fmaf(a.y, w1.z,
                               fmaf(a.z, w2.z, fmaf(a.w, w3.z, acc[c][p][2]))));
                acc[c][p][3] = fmaf(a.x, w0.w, fmaf(a.y, w1.w,
                               fmaf(a.z, w2.w, fmaf(a.w, w3.w, acc[c][p][3]))));
            }
        }
    }
}

// Hidden layer: accumulate + tanh chain + store all 5 channels (STS.128).
__device__ __forceinline__ void hidden5(const float* __restrict__ in,
                                        float* __restrict__ outp,
                                        const float* __restrict__ W,
                                        const float* __restrict__ b,
                                        int j4, int pp0)
{
    float acc[5][2][4];
    accum5(in, W, j4, pp0, acc);

    const float4 bb = *reinterpret_cast<const float4*>(&b[j4]);
    const float bj[4] = {bb.x, bb.y, bb.z, bb.w};

#pragma unroll
    for (int p = 0; p < 2; p++) {
        const int pp = pp0 + p;
        float4 o0, o1, o2, o3, o4;
        float* po0 = &o0.x; float* po1 = &o1.x; float* po2 = &o2.x;
        float* po3 = &o3.x; float* po4 = &o4.x;
#pragma unroll
        for (int u = 0; u < 4; u++) {
            float zv  = acc[0][p][u] + bj[u];
            float zgx = acc[1][p][u];
            float zgy = acc[2][p][u];
            float zxx = acc[3][p][u];
            float zyy = acc[4][p][u];
            float a  = my_tanh(zv);
            float t1 = 1.0f - a * a;
            float t2 = -2.0f * a * t1;
            po0[u] = a;
            po1[u] = t1 * zgx;
            po2[u] = t1 * zgy;
            po3[u] = fmaf(t2 * zgx, zgx, t1 * zxx);
            po4[u] = fmaf(t2 * zgy, zgy, t1 * zyy);
        }
        *reinterpret_cast<float4*>(&outp[(0 * TI + pp) * H + j4]) = o0;
        *reinterpret_cast<float4*>(&outp[(1 * TI + pp) * H + j4]) = o1;
        *reinterpret_cast<float4*>(&outp[(2 * TI + pp) * H + j4]) = o2;
        *reinterpret_cast<float4*>(&outp[(3 * TI + pp) * H + j4]) = o3;
        *reinterpret_cast<float4*>(&outp[(4 * TI + pp) * H + j4]) = o4;
    }
}

// ---------------------------------------------------------------------------
// Interior: Taylor-mode Laplacian (v, gx, gy, hxx, hyy) + squared residual.
// ---------------------------------------------------------------------------
__global__ __launch_bounds__(THREADS, 2)
void pinn_interior(const float* __restrict__ xy, const float* __restrict__ f,
                   const float* __restrict__ W0, const float* __restrict__ b0,
                   const float* __restrict__ W1, const float* __restrict__ b1,
                   const float* __restrict__ W2, const float* __restrict__ b2,
                   const float* __restrict__ W3, int n)
{
    extern __shared__ float sm[];
    float* A    = sm + SM_A;
    float* B    = sm + SM_B;
    float* sxy  = sm + SM_XY;
    float* slap = sm + SM_LAP;

    const int tid  = threadIdx.x;
    const int t    = tid & 31;       // unit group: j = 4t..4t+3
    const int j4   = t * 4;
    const int pp0  = (tid >> 5) * 2; // 8 warps x 2 points = 16 points
    const int base = blockIdx.x * TI;

    if (tid < TI * 2) {
        int pt = base + (tid >> 1);
        if (pt > n - 1) pt = n - 1;
        sxy[tid] = xy[pt * 2 + (tid & 1)];
    }
    __syncthreads();

    // ---- layer 0: (x,y) -> 128 with derivative seeding ----
    {
        const float4 wxv = *reinterpret_cast<const float4*>(&W0[j4]);
        const float4 wyv = *reinterpret_cast<const float4*>(&W0[H + j4]);
        const float4 bbv = *reinterpret_cast<const float4*>(&b0[j4]);
        const float wx[4] = {wxv.x, wxv.y, wxv.z, wxv.w};
        const float wy[4] = {wyv.x, wyv.y, wyv.z, wyv.w};
        const float bj[4] = {bbv.x, bbv.y, bbv.z, bbv.w};
#pragma unroll
        for (int p = 0; p < 2; p++) {
            const int pp = pp0 + p;
            const float x = sxy[pp * 2 + 0];
            const float y = sxy[pp * 2 + 1];
            float4 o0, o1, o2, o3, o4;
            float* po0 = &o0.x; float* po1 = &o1.x; float* po2 = &o2.x;
            float* po3 = &o3.x; float* po4 = &o4.x;
#pragma unroll
            for (int u = 0; u < 4; u++) {
                float zv = fmaf(x, wx[u], fmaf(y, wy[u], bj[u]));
                float a  = my_tanh(zv);
                float t1 = 1.0f - a * a;
                float t2 = -2.0f * a * t1;
                po0[u] = a;
                po1[u] = t1 * wx[u];
                po2[u] = t1 * wy[u];
                po3[u] = t2 * wx[u] * wx[u];
                po4[u] = t2 * wy[u] * wy[u];
            }
            *reinterpret_cast<float4*>(&A[(0 * TI + pp) * H + j4]) = o0;
            *reinterpret_cast<float4*>(&A[(1 * TI + pp) * H + j4]) = o1;
            *reinterpret_cast<float4*>(&A[(2 * TI + pp) * H + j4]) = o2;
            *reinterpret_cast<float4*>(&A[(3 * TI + pp) * H + j4]) = o3;
            *reinterpret_cast<float4*>(&A[(4 * TI + pp) * H + j4]) = o4;
        }
    }
    __syncthreads();

    hidden5(A, B, W1, b1, j4, pp0);
    __syncthreads();

    // ---- final hidden layer fused with output projection ----
    {
        float acc[5][2][4];
        accum5(B, W2, j4, pp0, acc);

        const float4 bbv = *reinterpret_cast<const float4*>(&b2[j4]);
        const float4 w3v = *reinterpret_cast<const float4*>(&W3[j4]);
        const float bj[4] = {bbv.x, bbv.y, bbv.z, bbv.w};
        const float w3[4] = {w3v.x, w3v.y, w3v.z, w3v.w};

#pragma unroll
        for (int p = 0; p < 2; p++) {
            float s = 0.0f;
#pragma unroll
            for (int u = 0; u < 4; u++) {
                float zv  = acc[0][p][u] + bj[u];
                float zgx = acc[1][p][u];
                float zgy = acc[2][p][u];
                float zxx = acc[3][p][u];
                float zyy = acc[4][p][u];
                float a  = my_tanh(zv);
                float t1 = 1.0f - a * a;
                float t2 = -2.0f * a * t1;
                float hxx = fmaf(t2 * zgx, zgx, t1 * zxx);
                float hyy = fmaf(t2 * zgy, zgy, t1 * zyy);
                s = fmaf(hxx + hyy, w3[u], s);
            }
            // warp-wide reduction over the 128 units
#pragma unroll
            for (int off = 16; off > 0; off >>= 1)
                s += __shfl_xor_sync(0xffffffffu, s, off);
            if (t == 0) slap[pp0 + p] = s;
        }
    }
    __syncthreads();

    if (tid == 0) {
        float ssum = 0.0f;
#pragma unroll
        for (int p = 0; p < TI; p++) {
            int idx = base + p;
            if (idx < n) {
                float d = slap[p] - f[idx];
                ssum = fmaf(d, d, ssum);
            }
        }
        g_part_int[blockIdx.x] = ssum;
    }
}

// ---------------------------------------------------------------------------
// Boundary: plain forward + squared residual partial sums (small workload).
// ---------------------------------------------------------------------------
__device__ __forceinline__ void hidden1(const float* __restrict__ in,
                                        float* __restrict__ outp,
                                        const float* __restrict__ W,
                                        const float* __restrict__ b,
                                        int j, int p0)
{
    float acc[TB / 2];
#pragma unroll
    for (int p = 0; p < TB / 2; p++) acc[p] = 0.0f;

#pragma unroll 1
    for (int k = 0; k < H; k += 4) {
        const float w0 = W[(k + 0) * H + j];
        const float w1 = W[(k + 1) * H + j];
        const float w2 = W[(k + 2) * H + j];
        const float w3 = W[(k + 3) * H + j];
#pragma unroll
        for (int p = 0; p < TB / 2; p++) {
            const float4 a = *reinterpret_cast<const float4*>(
                &in[(p0 + p) * H + k]);
            acc[p] = fmaf(a.x, w0,
                      fmaf(a.y, w1,
                       fmaf(a.z, w2,
                        fmaf(a.w, w3, acc[p]))));
        }
    }

    const float bj = b[j];
#pragma unroll
    for (int p = 0; p < TB / 2; p++)
        outp[(p0 + p) * H + j] = my_tanh(acc[p] + bj);
}

__global__ __launch_bounds__(THREADS)
void pinn_boundary(const float* __restrict__ xy, const float* __restrict__ g,
                   const float* __restrict__ W0, const float* __restrict__ b0,
                   const float* __restrict__ W1, const float* __restrict__ b1,
                   const float* __restrict__ W2, const float* __restrict__ b2,
                   const float* __restrict__ W3, const float* __restrict__ b3,
                   int n)
{
    __shared__ float A[TB * H];
    __shared__ float B[TB * H];
    __shared__ float sxy[TB * 2];
    __shared__ float red[TB];

    const int tid  = threadIdx.x;
    const int j    = tid & (H - 1);
    const int p0   = (tid >> 7) * (TB / 2);
    const int base = blockIdx.x * TB;

    if (tid < TB * 2) {
        int pt = base + (tid >> 1);
        if (pt > n - 1) pt = n - 1;
        sxy[tid] = xy[pt * 2 + (tid & 1)];
    }
    __syncthreads();

    {
        const float w0x = W0[j];
        const float w0y = W0[H + j];
        const float bj  = b0[j];
#pragma unroll
        for (int p = 0; p < TB / 2; p++) {
            const int pp = p0 + p;
            float x = sxy[pp * 2 + 0];
            float y = sxy[pp * 2 + 1];
            A[pp * H + j] = my_tanh(fmaf(x, w0x, fmaf(y, w0y, bj)));
        }
    }
    __syncthreads();

    hidden1(A, B, W1, b1, j, p0);
    __syncthreads();
    hidden1(B, A, W2, b2, j, p0);
    __syncthreads();

    if (tid < TB) {
        float v = b3[0];
        for (int k = 0; k < H; k++)
            v = fmaf(A[tid * H + k], W3[k], v);
        int idx = base + tid;
        if (idx < n) {
            float d = v - g[idx];
            red[tid] = d * d;
        } else {
            red[tid] = 0.0f;
        }
    }
    __syncthreads();

    if (tid == 0) {
        float s = 0.0f;
#pragma unroll
        for (int p = 0; p < TB; p++) s += red[p];
        g_part_bd[blockIdx.x] = s;
    }
}

// ---------------------------------------------------------------------------
// Final deterministic reduction -> out[0] = loss_bound, out[1] = loss_f
// ---------------------------------------------------------------------------
__global__ __launch_bounds__(THREADS)
void pinn_finalize(float* __restrict__ out, int nbi, int nbb,
                   int n_int, int n_bd)
{
    __shared__ float s[THREADS];
    const int tid = threadIdx.x;

    float a = 0.0f;
    for (int i = tid; i < nbi; i += THREADS) a += g_part_int[i];
    s[tid] = a;
    __syncthreads();
    for (int st = THREADS / 2; st > 0; st >>= 1) {
        if (tid < st) s[tid] += s[tid + st];
        __syncthreads();
    }
    float loss_f = 0.0f;
    if (tid == 0) loss_f = s[0] * (0.5f / (float)n_int);
    __syncthreads();

    float bsm = 0.0f;
    for (int i = tid; i < nbb; i += THREADS) bsm += g_part_bd[i];
    s[tid] = bsm;
    __syncthreads();
    for (int st = THREADS / 2; st > 0; st >>= 1) {
        if (tid < st) s[tid] += s[tid + st];
        __syncthreads();
    }
    if (tid == 0) {
        out[0] = s[0] * (0.5f / (float)n_bd); // loss_bound
        out[1] = loss_f;                      // loss_f
    }
}

// ---------------------------------------------------------------------------
extern "C" void kernel_launch(void* const* d_in, const int* in_sizes, int n_in,
                              void* d_out, int out_size)
{
    const float* xy_int = (const float*)d_in[0];
    const float* f      = (const float*)d_in[1];
    const float* xy_bd  = (const float*)d_in[2];
    const float* g      = (const float*)d_in[3];
    const float* W0     = (const float*)d_in[4];
    const float* b0     = (const float*)d_in[5];
    const float* W1     = (const float*)d_in[6];
    const float* b1     = (const float*)d_in[7];
    const float* W2     = (const float*)d_in[8];
    const float* b2     = (const float*)d_in[9];
    const float* W3     = (const float*)d_in[10];
    const float* b3     = (const float*)d_in[11];

    const int n_int = in_sizes[0] / 2;
    const int n_bd  = in_sizes[2] / 2;

    int gi = (n_int + TI - 1) / TI;
    int gb = (n_bd + TB - 1) / TB;
    if (gi > 65536) gi = 65536; // scratch bound (dataset: 16384)
    if (gb > 8192)  gb = 8192;  // scratch bound (dataset: 512)

    const int smem_bytes = SM_FLOATS * (int)sizeof(float); // 82112 B

    cudaFuncSetAttribute(pinn_interior,
                         cudaFuncAttributeMaxDynamicSharedMemorySize,
                         smem_bytes);

    pinn_interior<<<gi, THREADS, smem_bytes>>>(xy_int, f, W0, b0, W1, b1,
                                               W2, b2, W3, n_int);
    pinn_boundary<<<gb, THREADS>>>(xy_bd, g, W0, b0, W1, b1, W2, b2, W3, b3,
                                   n_bd);
    pinn_finalize<<<1, THREADS>>>((float*)d_out, gi, gb, n_int, n_bd);
}

// round 3
// speedup vs baseline: 1.6208x; 1.1105x over previous
#include <cuda_runtime.h>
#include <math.h>

#define H       128
#define TI      16    // interior points per block (2 per warp)
#define TB      32    // boundary points per block
#define THREADS 256

// Per-block partial sums (deterministic two-stage reduction; no device mallocs)
__device__ float g_part_int[65536];
__device__ float g_part_bd[8192];

// Accurate tanh independent of -use_fast_math lowering of tanhf.
__device__ __forceinline__ float my_tanh(float x)
{
    float ax = fabsf(x);
    float t  = __expf(-2.0f * ax);
    float r  = (1.0f - t) / (1.0f + t);
    return copysignf(r, x);
}

// ---------------------------------------------------------------------------
// Accumulate 5 channels x 2 points x 4 units. Warp-private data:
// lane t handles units j4 = 4t..4t+3; the warp owns points pp0, pp0+1.
// Activations: lane-uniform LDS.128 broadcasts; weights: warp-contiguous
// LDG.128 (512 B/row, L1-resident).
// ---------------------------------------------------------------------------
__device__ __forceinline__ void accum5(const float* __restrict__ in,
                                       const float* __restrict__ W,
                                       int j4, int pp0,
                                       float acc[5][2][4])
{
#pragma unroll
    for (int c = 0; c < 5; c++)
#pragma unroll
        for (int p = 0; p < 2; p++)
#pragma unroll
            for (int u = 0; u < 4; u++) acc[c][p][u] = 0.0f;

#pragma unroll 1
    for (int k = 0; k < H; k += 4) {
        const float4 w0 = *reinterpret_cast<const float4*>(&W[(k + 0) * H + j4]);
        const float4 w1 = *reinterpret_cast<const float4*>(&W[(k + 1) * H + j4]);
        const float4 w2 = *reinterpret_cast<const float4*>(&W[(k + 2) * H + j4]);
        const float4 w3 = *reinterpret_cast<const float4*>(&W[(k + 3) * H + j4]);
#pragma unroll
        for (int c = 0; c < 5; c++) {
#pragma unroll
            for (int p = 0; p < 2; p++) {
                const float4 a = *reinterpret_cast<const float4*>(
                    &in[(c * TI + pp0 + p) * H + k]);
                acc[c][p][0] = fmaf(a.x, w0.x, fmaf(a.y, w1.x,
                               fmaf(a.z, w2.x, fmaf(a.w, w3.x, acc[c][p][0]))));
                acc[c][p][1] = fmaf(a.x, w0.y, fmaf(a.y, w1.y,
                               fmaf(a.z, w2.y, fmaf(a.w, w3.y, acc[c][p][1]))));
                acc[c][p][2] = fmaf(a.x, w0.z, fmaf(a.y, w1.z,
                               fmaf(a.z, w2.z, fmaf(a.w, w3.z, acc[c][p][2]))));
                acc[c][p][3] = fmaf(a.x, w0.w, fmaf(a.y, w1.w,
                               fmaf(a.z, w2.w, fmaf(a.w, w3.w, acc[c][p][3]))));
            }
        }
    }
}

// ---------------------------------------------------------------------------
// Interior: Taylor-mode Laplacian (v, gx, gy, hxx, hyy), warp-autonomous:
// no __syncthreads in the pipeline, single in-place activation buffer.
// ---------------------------------------------------------------------------
__global__ __launch_bounds__(THREADS, 3)
void pinn_interior(const float* __restrict__ xy, const float* __restrict__ f,
                   const float* __restrict__ W0, const float* __restrict__ b0,
                   const float* __restrict__ W1, const float* __restrict__ b1,
                   const float* __restrict__ W2, const float* __restrict__ b2,
                   const float* __restrict__ W3, int n)
{
    __shared__ float A[5 * TI * H];   // 40 KB, warp-private row blocks
    __shared__ float slap[TI];

    const int tid  = threadIdx.x;
    const int t    = tid & 31;       // unit group: j = 4t..4t+3
    const int j4   = t * 4;
    const int pp0  = (tid >> 5) * 2; // warp w owns points pp0, pp0+1
    const int base = blockIdx.x * TI;

    // per-warp broadcast loads of this warp's two points
    int pt0 = base + pp0;     if (pt0 > n - 1) pt0 = n - 1;
    int pt1 = base + pp0 + 1; if (pt1 > n - 1) pt1 = n - 1;
    float xin[2], yin[2];
    xin[0] = __ldg(&xy[pt0 * 2 + 0]); yin[0] = __ldg(&xy[pt0 * 2 + 1]);
    xin[1] = __ldg(&xy[pt1 * 2 + 0]); yin[1] = __ldg(&xy[pt1 * 2 + 1]);

    // ---- layer 0: (x,y) -> 128 with derivative seeding ----
    {
        const float4 wxv = *reinterpret_cast<const float4*>(&W0[j4]);
        const float4 wyv = *reinterpret_cast<const float4*>(&W0[H + j4]);
        const float4 bbv = *reinterpret_cast<const float4*>(&b0[j4]);
        const float wx[4] = {wxv.x, wxv.y, wxv.z, wxv.w};
        const float wy[4] = {wyv.x, wyv.y, wyv.z, wyv.w};
        const float bj[4] = {bbv.x, bbv.y, bbv.z, bbv.w};
#pragma unroll
        for (int p = 0; p < 2; p++) {
            const int pp = pp0 + p;
            float4 o0, o1, o2, o3, o4;
            float* po0 = &o0.x; float* po1 = &o1.x; float* po2 = &o2.x;
            float* po3 = &o3.x; float* po4 = &o4.x;
#pragma unroll
            for (int u = 0; u < 4; u++) {
                float zv = fmaf(xin[p], wx[u], fmaf(yin[p], wy[u], bj[u]));
                float a  = my_tanh(zv);
                float t1 = 1.0f - a * a;
                float t2 = -2.0f * a * t1;
                po0[u] = a;
                po1[u] = t1 * wx[u];
                po2[u] = t1 * wy[u];
                po3[u] = t2 * wx[u] * wx[u];
                po4[u] = t2 * wy[u] * wy[u];
            }
            *reinterpret_cast<float4*>(&A[(0 * TI + pp) * H + j4]) = o0;
            *reinterpret_cast<float4*>(&A[(1 * TI + pp) * H + j4]) = o1;
            *reinterpret_cast<float4*>(&A[(2 * TI + pp) * H + j4]) = o2;
            *reinterpret_cast<float4*>(&A[(3 * TI + pp) * H + j4]) = o3;
            *reinterpret_cast<float4*>(&A[(4 * TI + pp) * H + j4]) = o4;
        }
    }
    __syncwarp();

    // ---- layer 1 (in-place: read A, then overwrite A) ----
    {
        float acc[5][2][4];
        accum5(A, W1, j4, pp0, acc);
        __syncwarp();

        const float4 bb = *reinterpret_cast<const float4*>(&b1[j4]);
        const float bj[4] = {bb.x, bb.y, bb.z, bb.w};
#pragma unroll
        for (int p = 0; p < 2; p++) {
            const int pp = pp0 + p;
            float4 o0, o1, o2, o3, o4;
            float* po0 = &o0.x; float* po1 = &o1.x; float* po2 = &o2.x;
            float* po3 = &o3.x; float* po4 = &o4.x;
#pragma unroll
            for (int u = 0; u < 4; u++) {
                float zv  = acc[0][p][u] + bj[u];
                float zgx = acc[1][p][u];
                float zgy = acc[2][p][u];
                float zxx = acc[3][p][u];
                float zyy = acc[4][p][u];
                float a  = my_tanh(zv);
                float t1 = 1.0f - a * a;
                float t2 = -2.0f * a * t1;
                po0[u] = a;
                po1[u] = t1 * zgx;
                po2[u] = t1 * zgy;
                po3[u] = fmaf(t2 * zgx, zgx, t1 * zxx);
                po4[u] = fmaf(t2 * zgy, zgy, t1 * zyy);
            }
            *reinterpret_cast<float4*>(&A[(0 * TI + pp) * H + j4]) = o0;
            *reinterpret_cast<float4*>(&A[(1 * TI + pp) * H + j4]) = o1;
            *reinterpret_cast<float4*>(&A[(2 * TI + pp) * H + j4]) = o2;
            *reinterpret_cast<float4*>(&A[(3 * TI + pp) * H + j4]) = o3;
            *reinterpret_cast<float4*>(&A[(4 * TI + pp) * H + j4]) = o4;
        }
    }
    __syncwarp();

    // ---- layer 2 fused with output projection ----
    {
        float acc[5][2][4];
        accum5(A, W2, j4, pp0, acc);

        const float4 bbv = *reinterpret_cast<const float4*>(&b2[j4]);
        const float4 w3v = *reinterpret_cast<const float4*>(&W3[j4]);
        const float bj[4] = {bbv.x, bbv.y, bbv.z, bbv.w};
        const float w3[4] = {w3v.x, w3v.y, w3v.z, w3v.w};

#pragma unroll
        for (int p = 0; p < 2; p++) {
            float s = 0.0f;
#pragma unroll
            for (int u = 0; u < 4; u++) {
                float zv  = acc[0][p][u] + bj[u];
                float zgx = acc[1][p][u];
                float zgy = acc[2][p][u];
                float zxx = acc[3][p][u];
                float zyy = acc[4][p][u];
                float a  = my_tanh(zv);
                float t1 = 1.0f - a * a;
                float t2 = -2.0f * a * t1;
                float hxx = fmaf(t2 * zgx, zgx, t1 * zxx);
                float hyy = fmaf(t2 * zgy, zgy, t1 * zyy);
                s = fmaf(hxx + hyy, w3[u], s);
            }
#pragma unroll
            for (int off = 16; off > 0; off >>= 1)
                s += __shfl_xor_sync(0xffffffffu, s, off);
            if (t == 0) slap[pp0 + p] = s;
        }
    }
    __syncthreads();   // only block-wide barrier: before final reduction

    if (tid == 0) {
        float ssum = 0.0f;
#pragma unroll
        for (int p = 0; p < TI; p++) {
            int idx = base + p;
            if (idx < n) {
                float d = slap[p] - f[idx];
                ssum = fmaf(d, d, ssum);
            }
        }
        g_part_int[blockIdx.x] = ssum;
    }
}

// ---------------------------------------------------------------------------
// Boundary: plain forward + squared residual partial sums (small workload).
// ---------------------------------------------------------------------------
__device__ __forceinline__ void hidden1(const float* __restrict__ in,
                                        float* __restrict__ outp,
                                        const float* __restrict__ W,
                                        const float* __restrict__ b,
                                        int j, int p0)
{
    float acc[TB / 2];
#pragma unroll
    for (int p = 0; p < TB / 2; p++) acc[p] = 0.0f;

#pragma unroll 1
    for (int k = 0; k < H; k += 4) {
        const float w0 = W[(k + 0) * H + j];
        const float w1 = W[(k + 1) * H + j];
        const float w2 = W[(k + 2) * H + j];
        const float w3 = W[(k + 3) * H + j];
#pragma unroll
        for (int p = 0; p < TB / 2; p++) {
            const float4 a = *reinterpret_cast<const float4*>(
                &in[(p0 + p) * H + k]);
            acc[p] = fmaf(a.x, w0,
                      fmaf(a.y, w1,
                       fmaf(a.z, w2,
                        fmaf(a.w, w3, acc[p]))));
        }
    }

    const float bj = b[j];
#pragma unroll
    for (int p = 0; p < TB / 2; p++)
        outp[(p0 + p) * H + j] = my_tanh(acc[p] + bj);
}

__global__ __launch_bounds__(THREADS)
void pinn_boundary(const float* __restrict__ xy, const float* __restrict__ g,
                   const float* __restrict__ W0, const float* __restrict__ b0,
                   const float* __restrict__ W1, const float* __restrict__ b1,
                   const float* __restrict__ W2, const float* __restrict__ b2,
                   const float* __restrict__ W3, const float* __restrict__ b3,
                   int n)
{
    __shared__ float A[TB * H];
    __shared__ float B[TB * H];
    __shared__ float sxy[TB * 2];
    __shared__ float red[TB];

    const int tid  = threadIdx.x;
    const int j    = tid & (H - 1);
    const int p0   = (tid >> 7) * (TB / 2);
    const int base = blockIdx.x * TB;

    if (tid < TB * 2) {
        int pt = base + (tid >> 1);
        if (pt > n - 1) pt = n - 1;
        sxy[tid] = xy[pt * 2 + (tid & 1)];
    }
    __syncthreads();

    {
        const float w0x = W0[j];
        const float w0y = W0[H + j];
        const float bj  = b0[j];
#pragma unroll
        for (int p = 0; p < TB / 2; p++) {
            const int pp = p0 + p;
            float x = sxy[pp * 2 + 0];
            float y = sxy[pp * 2 + 1];
            A[pp * H + j] = my_tanh(fmaf(x, w0x, fmaf(y, w0y, bj)));
        }
    }
    __syncthreads();

    hidden1(A, B, W1, b1, j, p0);
    __syncthreads();
    hidden1(B, A, W2, b2, j, p0);
    __syncthreads();

    if (tid < TB) {
        float v = b3[0];
        for (int k = 0; k < H; k++)
            v = fmaf(A[tid * H + k], W3[k], v);
        int idx = base + tid;
        if (idx < n) {
            float d = v - g[idx];
            red[tid] = d * d;
        } else {
            red[tid] = 0.0f;
        }
    }
    __syncthreads();

    if (tid == 0) {
        float s = 0.0f;
#pragma unroll
        for (int p = 0; p < TB; p++) s += red[p];
        g_part_bd[blockIdx.x] = s;
    }
}

// ---------------------------------------------------------------------------
// Final deterministic reduction -> out[0] = loss_bound, out[1] = loss_f
// ---------------------------------------------------------------------------
__global__ __launch_bounds__(THREADS)
void pinn_finalize(float* __restrict__ out, int nbi, int nbb,
                   int n_int, int n_bd)
{
    __shared__ float s[THREADS];
    const int tid = threadIdx.x;

    float a = 0.0f;
    for (int i = tid; i < nbi; i += THREADS) a += g_part_int[i];
    s[tid] = a;
    __syncthreads();
    for (int st = THREADS / 2; st > 0; st >>= 1) {
        if (tid < st) s[tid] += s[tid + st];
        __syncthreads();
    }
    float loss_f = 0.0f;
    if (tid == 0) loss_f = s[0] * (0.5f / (float)n_int);
    __syncthreads();

    float bsm = 0.0f;
    for (int i = tid; i < nbb; i += THREADS) bsm += g_part_bd[i];
    s[tid] = bsm;
    __syncthreads();
    for (int st = THREADS / 2; st > 0; st >>= 1) {
        if (tid < st) s[tid] += s[tid + st];
        __syncthreads();
    }
    if (tid == 0) {
        out[0] = s[0] * (0.5f / (float)n_bd); // loss_bound
        out[1] = loss_f;                      // loss_f
    }
}

// ---------------------------------------------------------------------------
extern "C" void kernel_launch(void* const* d_in, const int* in_sizes, int n_in,
                              void* d_out, int out_size)
{
    const float* xy_int = (const float*)d_in[0];
    const float* f      = (const float*)d_in[1];
    const float* xy_bd  = (const float*)d_in[2];
    const float* g      = (const float*)d_in[3];
    const float* W0     = (const float*)d_in[4];
    const float* b0     = (const float*)d_in[5];
    const float* W1     = (const float*)d_in[6];
    const float* b1     = (const float*)d_in[7];
    const float* W2     = (const float*)d_in[8];
    const float* b2     = (const float*)d_in[9];
    const float* W3     = (const float*)d_in[10];
    const float* b3     = (const float*)d_in[11];

    const int n_int = in_sizes[0] / 2;
    const int n_bd  = in_sizes[2] / 2;

    int gi = (n_int + TI - 1) / TI;
    int gb = (n_bd + TB - 1) / TB;
    if (gi > 65536) gi = 65536; // scratch bound (dataset: 16384)
    if (gb > 8192)  gb = 8192;  // scratch bound (dataset: 512)

    pinn_interior<<<gi, THREADS>>>(xy_int, f, W0, b0, W1, b1, W2, b2, W3,
                                   n_int);
    pinn_boundary<<<gb, THREADS>>>(xy_bd, g, W0, b0, W1, b1, W2, b2, W3, b3,
                                   n_bd);
    pinn_finalize<<<1, THREADS>>>((float*)d_out, gi, gb, n_int, n_bd);
}

// round 4
// speedup vs baseline: 1.9189x; 1.1839x over previous
#include <cuda_runtime.h>
#include <math.h>

#define H       128
#define TI      24    // interior points per block (3 per warp)
#define TB      32    // boundary points per block
#define THREADS 256
#define PW      3     // points per warp

// Per-block partial sums (deterministic two-stage reduction; no device mallocs)
__device__ float g_part_int[65536];
__device__ float g_part_bd[8192];

// Accurate tanh independent of -use_fast_math lowering of tanhf.
__device__ __forceinline__ float my_tanh(float x)
{
    float ax = fabsf(x);
    float t  = __expf(-2.0f * ax);
    float r  = (1.0f - t) / (1.0f + t);
    return copysignf(r, x);
}

// ---------------------------------------------------------------------------
// Accumulate 4 channels (v, gx, gy, L) x 3 points x 4 units. Warp-private:
// lane t handles units j4 = 4t..4t+3; the warp owns points pp0..pp0+2.
// Activations: lane-uniform LDS.128 broadcasts; weights: warp-contiguous
// LDG.128 (512 B/row, L1-resident).
// ---------------------------------------------------------------------------
__device__ __forceinline__ void accum4(const float* __restrict__ in,
                                       const float* __restrict__ W,
                                       int j4, int pp0,
                                       float acc[4][PW][4])
{
#pragma unroll
    for (int c = 0; c < 4; c++)
#pragma unroll
        for (int p = 0; p < PW; p++)
#pragma unroll
            for (int u = 0; u < 4; u++) acc[c][p][u] = 0.0f;

#pragma unroll 1
    for (int k = 0; k < H; k += 4) {
        const float4 w0 = *reinterpret_cast<const float4*>(&W[(k + 0) * H + j4]);
        const float4 w1 = *reinterpret_cast<const float4*>(&W[(k + 1) * H + j4]);
        const float4 w2 = *reinterpret_cast<const float4*>(&W[(k + 2) * H + j4]);
        const float4 w3 = *reinterpret_cast<const float4*>(&W[(k + 3) * H + j4]);
#pragma unroll
        for (int c = 0; c < 4; c++) {
#pragma unroll
            for (int p = 0; p < PW; p++) {
                const float4 a = *reinterpret_cast<const float4*>(
                    &in[(c * TI + pp0 + p) * H + k]);
                acc[c][p][0] = fmaf(a.x, w0.x, fmaf(a.y, w1.x,
                               fmaf(a.z, w2.x, fmaf(a.w, w3.x, acc[c][p][0]))));
                acc[c][p][1] = fmaf(a.x, w0.y, fmaf(a.y, w1.y,
                               fmaf(a.z, w2.y, fmaf(a.w, w3.y, acc[c][p][1]))));
                acc[c][p][2] = fmaf(a.x, w0.z, fmaf(a.y, w1.z,
                               fmaf(a.z, w2.z, fmaf(a.w, w3.z, acc[c][p][2]))));
                acc[c][p][3] = fmaf(a.x, w0.w, fmaf(a.y, w1.w,
                               fmaf(a.z, w2.w, fmaf(a.w, w3.w, acc[c][p][3]))));
            }
        }
    }
}

// ---------------------------------------------------------------------------
// Interior: 4-channel Taylor-mode Laplacian (v, gx, gy, L = uxx+uyy).
// Warp-autonomous pipeline: no __syncthreads between layers.
// ---------------------------------------------------------------------------
__global__ __launch_bounds__(THREADS, 3)
void pinn_interior(const float* __restrict__ xy, const float* __restrict__ f,
                   const float* __restrict__ W0, const float* __restrict__ b0,
                   const float* __restrict__ W1, const float* __restrict__ b1,
                   const float* __restrict__ W2, const float* __restrict__ b2,
                   const float* __restrict__ W3, int n)
{
    __shared__ float A[4 * TI * H];   // 48 KB, warp-private row blocks

    const int tid  = threadIdx.x;
    const int t    = tid & 31;        // unit group: j = 4t..4t+3
    const int j4   = t * 4;
    const int pp0  = (tid >> 5) * PW; // warp w owns points pp0..pp0+2
    const int base = blockIdx.x * TI;

    // per-warp broadcast loads of this warp's points
    float xin[PW], yin[PW];
#pragma unroll
    for (int p = 0; p < PW; p++) {
        int pt = base + pp0 + p; if (pt > n - 1) pt = n - 1;
        xin[p] = __ldg(&xy[pt * 2 + 0]);
        yin[p] = __ldg(&xy[pt * 2 + 1]);
    }

    // ---- layer 0: (x,y) -> 128 with derivative seeding ----
    {
        const float4 wxv = *reinterpret_cast<const float4*>(&W0[j4]);
        const float4 wyv = *reinterpret_cast<const float4*>(&W0[H + j4]);
        const float4 bbv = *reinterpret_cast<const float4*>(&b0[j4]);
        const float wx[4] = {wxv.x, wxv.y, wxv.z, wxv.w};
        const float wy[4] = {wyv.x, wyv.y, wyv.z, wyv.w};
        const float bj[4] = {bbv.x, bbv.y, bbv.z, bbv.w};
#pragma unroll
        for (int p = 0; p < PW; p++) {
            const int pp = pp0 + p;
            float4 o0, o1, o2, o3;
            float* po0 = &o0.x; float* po1 = &o1.x;
            float* po2 = &o2.x; float* po3 = &o3.x;
#pragma unroll
            for (int u = 0; u < 4; u++) {
                float zv = fmaf(xin[p], wx[u], fmaf(yin[p], wy[u], bj[u]));
                float a  = my_tanh(zv);
                float t1 = 1.0f - a * a;
                float t2 = -2.0f * a * t1;
                po0[u] = a;
                po1[u] = t1 * wx[u];
                po2[u] = t1 * wy[u];
                po3[u] = t2 * fmaf(wx[u], wx[u], wy[u] * wy[u]); // L seed
            }
            *reinterpret_cast<float4*>(&A[(0 * TI + pp) * H + j4]) = o0;
            *reinterpret_cast<float4*>(&A[(1 * TI + pp) * H + j4]) = o1;
            *reinterpret_cast<float4*>(&A[(2 * TI + pp) * H + j4]) = o2;
            *reinterpret_cast<float4*>(&A[(3 * TI + pp) * H + j4]) = o3;
        }
    }
    __syncwarp();

    // ---- layer 1 (in-place: read A, then overwrite A) ----
    {
        float acc[4][PW][4];
        accum4(A, W1, j4, pp0, acc);
        __syncwarp();

        const float4 bb = *reinterpret_cast<const float4*>(&b1[j4]);
        const float bj[4] = {bb.x, bb.y, bb.z, bb.w};
#pragma unroll
        for (int p = 0; p < PW; p++) {
            const int pp = pp0 + p;
            float4 o0, o1, o2, o3;
            float* po0 = &o0.x; float* po1 = &o1.x;
            float* po2 = &o2.x; float* po3 = &o3.x;
#pragma unroll
            for (int u = 0; u < 4; u++) {
                float zv  = acc[0][p][u] + bj[u];
                float zgx = acc[1][p][u];
                float zgy = acc[2][p][u];
                float zL  = acc[3][p][u];
                float a  = my_tanh(zv);
                float t1 = 1.0f - a * a;
                float t2 = -2.0f * a * t1;
                po0[u] = a;
                po1[u] = t1 * zgx;
                po2[u] = t1 * zgy;
                po3[u] = fmaf(t2, fmaf(zgx, zgx, zgy * zgy), t1 * zL);
            }
            *reinterpret_cast<float4*>(&A[(0 * TI + pp) * H + j4]) = o0;
            *reinterpret_cast<float4*>(&A[(1 * TI + pp) * H + j4]) = o1;
            *reinterpret_cast<float4*>(&A[(2 * TI + pp) * H + j4]) = o2;
            *reinterpret_cast<float4*>(&A[(3 * TI + pp) * H + j4]) = o3;
        }
    }
    __syncwarp();

    // ---- layer 2 fused with output projection: lap = W3 . L_out ----
    {
        float acc[4][PW][4];
        accum4(A, W2, j4, pp0, acc);

        const float4 bbv = *reinterpret_cast<const float4*>(&b2[j4]);
        const float4 w3v = *reinterpret_cast<const float4*>(&W3[j4]);
        const float bj[4] = {bbv.x, bbv.y, bbv.z, bbv.w};
        const float w3[4] = {w3v.x, w3v.y, w3v.z, w3v.w};

#pragma unroll
        for (int p = 0; p < PW; p++) {
            float s = 0.0f;
#pragma unroll
            for (int u = 0; u < 4; u++) {
                float zv  = acc[0][p][u] + bj[u];
                float zgx = acc[1][p][u];
                float zgy = acc[2][p][u];
                float zL  = acc[3][p][u];
                float a  = my_tanh(zv);
                float t1 = 1.0f - a * a;
                float t2 = -2.0f * a * t1;
                float L  = fmaf(t2, fmaf(zgx, zgx, zgy * zgy), t1 * zL);
                s = fmaf(L, w3[u], s);
            }
#pragma unroll
            for (int off = 16; off > 0; off >>= 1)
                s += __shfl_xor_sync(0xffffffffu, s, off);
            // stash lap in this warp's (now dead) channel-0 row
            if (t == 0) A[(0 * TI + pp0 + p) * H] = s;
        }
    }
    __syncthreads();   // only block-wide barrier: before final reduction

    if (tid == 0) {
        float ssum = 0.0f;
#pragma unroll
        for (int p = 0; p < TI; p++) {
            int idx = base + p;
            if (idx < n) {
                float d = A[p * H] - f[idx];
                ssum = fmaf(d, d, ssum);
            }
        }
        g_part_int[blockIdx.x] = ssum;
    }
}

// ---------------------------------------------------------------------------
// Boundary: plain forward + squared residual partial sums (small workload).
// ---------------------------------------------------------------------------
__device__ __forceinline__ void hidden1(const float* __restrict__ in,
                                        float* __restrict__ outp,
                                        const float* __restrict__ W,
                                        const float* __restrict__ b,
                                        int j, int p0)
{
    float acc[TB / 2];
#pragma unroll
    for (int p = 0; p < TB / 2; p++) acc[p] = 0.0f;

#pragma unroll 1
    for (int k = 0; k < H; k += 4) {
        const float w0 = W[(k + 0) * H + j];
        const float w1 = W[(k + 1) * H + j];
        const float w2 = W[(k + 2) * H + j];
        const float w3 = W[(k + 3) * H + j];
#pragma unroll
        for (int p = 0; p < TB / 2; p++) {
            const float4 a = *reinterpret_cast<const float4*>(
                &in[(p0 + p) * H + k]);
            acc[p] = fmaf(a.x, w0,
                      fmaf(a.y, w1,
                       fmaf(a.z, w2,
                        fmaf(a.w, w3, acc[p]))));
        }
    }

    const float bj = b[j];
#pragma unroll
    for (int p = 0; p < TB / 2; p++)
        outp[(p0 + p) * H + j] = my_tanh(acc[p] + bj);
}

__global__ __launch_bounds__(THREADS)
void pinn_boundary(const float* __restrict__ xy, const float* __restrict__ g,
                   const float* __restrict__ W0, const float* __restrict__ b0,
                   const float* __restrict__ W1, const float* __restrict__ b1,
                   const float* __restrict__ W2, const float* __restrict__ b2,
                   const float* __restrict__ W3, const float* __restrict__ b3,
                   int n)
{
    __shared__ float A[TB * H];
    __shared__ float B[TB * H];
    __shared__ float sxy[TB * 2];
    __shared__ float red[TB];

    const int tid  = threadIdx.x;
    const int j    = tid & (H - 1);
    const int p0   = (tid >> 7) * (TB / 2);
    const int base = blockIdx.x * TB;

    if (tid < TB * 2) {
        int pt = base + (tid >> 1);
        if (pt > n - 1) pt = n - 1;
        sxy[tid] = xy[pt * 2 + (tid & 1)];
    }
    __syncthreads();

    {
        const float w0x = W0[j];
        const float w0y = W0[H + j];
        const float bj  = b0[j];
#pragma unroll
        for (int p = 0; p < TB / 2; p++) {
            const int pp = p0 + p;
            float x = sxy[pp * 2 + 0];
            float y = sxy[pp * 2 + 1];
            A[pp * H + j] = my_tanh(fmaf(x, w0x, fmaf(y, w0y, bj)));
        }
    }
    __syncthreads();

    hidden1(A, B, W1, b1, j, p0);
    __syncthreads();
    hidden1(B, A, W2, b2, j, p0);
    __syncthreads();

    if (tid < TB) {
        float v = b3[0];
        for (int k = 0; k < H; k++)
            v = fmaf(A[tid * H + k], W3[k], v);
        int idx = base + tid;
        if (idx < n) {
            float d = v - g[idx];
            red[tid] = d * d;
        } else {
            red[tid] = 0.0f;
        }
    }
    __syncthreads();

    if (tid == 0) {
        float s = 0.0f;
#pragma unroll
        for (int p = 0; p < TB; p++) s += red[p];
        g_part_bd[blockIdx.x] = s;
    }
}

// ---------------------------------------------------------------------------
// Final deterministic reduction -> out[0] = loss_bound, out[1] = loss_f
// ---------------------------------------------------------------------------
__global__ __launch_bounds__(THREADS)
void pinn_finalize(float* __restrict__ out, int nbi, int nbb,
                   int n_int, int n_bd)
{
    __shared__ float s[THREADS];
    const int tid = threadIdx.x;

    float a = 0.0f;
    for (int i = tid; i < nbi; i += THREADS) a += g_part_int[i];
    s[tid] = a;
    __syncthreads();
    for (int st = THREADS / 2; st > 0; st >>= 1) {
        if (tid < st) s[tid] += s[tid + st];
        __syncthreads();
    }
    float loss_f = 0.0f;
    if (tid == 0) loss_f = s[0] * (0.5f / (float)n_int);
    __syncthreads();

    float bsm = 0.0f;
    for (int i = tid; i < nbb; i += THREADS) bsm += g_part_bd[i];
    s[tid] = bsm;
    __syncthreads();
    for (int st = THREADS / 2; st > 0; st >>= 1) {
        if (tid < st) s[tid] += s[tid + st];
        __syncthreads();
    }
    if (tid == 0) {
        out[0] = s[0] * (0.5f / (float)n_bd); // loss_bound
        out[1] = loss_f;                      // loss_f
    }
}

// ---------------------------------------------------------------------------
extern "C" void kernel_launch(void* const* d_in, const int* in_sizes, int n_in,
                              void* d_out, int out_size)
{
    const float* xy_int = (const float*)d_in[0];
    const float* f      = (const float*)d_in[1];
    const float* xy_bd  = (const float*)d_in[2];
    const float* g      = (const float*)d_in[3];
    const float* W0     = (const float*)d_in[4];
    const float* b0     = (const float*)d_in[5];
    const float* W1     = (const float*)d_in[6];
    const float* b1     = (const float*)d_in[7];
    const float* W2     = (const float*)d_in[8];
    const float* b2     = (const float*)d_in[9];
    const float* W3     = (const float*)d_in[10];
    const float* b3     = (const float*)d_in[11];

    const int n_int = in_sizes[0] / 2;
    const int n_bd  = in_sizes[2] / 2;

    int gi = (n_int + TI - 1) / TI;
    int gb = (n_bd + TB - 1) / TB;
    if (gi > 65536) gi = 65536; // scratch bound (dataset: 10923)
    if (gb > 8192)  gb = 8192;  // scratch bound (dataset: 512)

    pinn_interior<<<gi, THREADS>>>(xy_int, f, W0, b0, W1, b1, W2, b2, W3,
                                   n_int);
    pinn_boundary<<<gb, THREADS>>>(xy_bd, g, W0, b0, W1, b1, W2, b2, W3, b3,
                                   n_bd);
    pinn_finalize<<<1, THREADS>>>((float*)d_out, gi, gb, n_int, n_bd);
}